// round 3
// baseline (speedup 1.0000x reference)
#include <cuda_runtime.h>
#include <math.h>

// Problem constants
#define Bb 4
#define Tt 2048
#define Dd 2048
#define DH 1024
#define KK 16
#define NH 16
#define HD 128
#define BT (Bb*Tt)          // 8192 rows
#define KPAD 1032           // dh+1 padded to multiple of 8

// ---------------- scratch (device globals; no allocation) ----------------
__device__ float g_S0[(size_t)BT * Dd];     // ln outputs / ctx
__device__ float g_S1[(size_t)BT * Dd];     // sheaf pre / Q
__device__ float g_repr[64 * Dd];           // gist_repr
__device__ float g_Kh[64 * Dd];
__device__ float g_Vv[64 * Dd];
__device__ float g_packin[64 * KPAD];
__device__ float g_Wpad[Dd * KPAD];
__device__ float g_shc[4 * DH];
__device__ float g_shs[4 * DH];
__device__ float g_gc[Bb * DH];
__device__ float g_gs[Bb * DH];

// ---------------- block reduction (sum of two values) ----------------
__device__ __forceinline__ void block_reduce2(float& a, float& b, float* sh)
{
    __syncthreads();   // protect shared reuse across consecutive calls
#pragma unroll
    for (int o = 16; o > 0; o >>= 1) {
        a += __shfl_xor_sync(0xffffffffu, a, o);
        b += __shfl_xor_sync(0xffffffffu, b, o);
    }
    int warp = threadIdx.x >> 5, lane = threadIdx.x & 31;
    if (lane == 0) { sh[warp] = a; sh[8 + warp] = b; }
    __syncthreads();
    if (threadIdx.x < 32) {
        float aa = (lane < 8) ? sh[lane] : 0.f;
        float bb = (lane < 8) ? sh[8 + lane] : 0.f;
#pragma unroll
        for (int o = 4; o > 0; o >>= 1) {
            aa += __shfl_xor_sync(0xffffffffu, aa, o);
            bb += __shfl_xor_sync(0xffffffffu, bb, o);
        }
        if (lane == 0) { sh[16] = aa; sh[17] = bb; }
    }
    __syncthreads();
    a = sh[16]; b = sh[17];
}

// ---------------- LayerNorm: y = LN(x)*w + b, one block per row ----------------
__global__ void __launch_bounds__(256) ln_kernel(const float* __restrict__ x,
                                                 float* __restrict__ y,
                                                 const float* __restrict__ w,
                                                 const float* __restrict__ b)
{
    __shared__ float sh[32];
    size_t row = blockIdx.x;
    const float* xr = x + row * Dd;
    float v[8]; float s = 0.f, s2 = 0.f;
#pragma unroll
    for (int i = 0; i < 8; i++) {
        v[i] = xr[threadIdx.x + (i << 8)];
        s += v[i]; s2 += v[i] * v[i];
    }
    block_reduce2(s, s2, sh);
    float mu = s * (1.f / Dd);
    float inv = rsqrtf(s2 * (1.f / Dd) - mu * mu + 1e-5f);
    float* yr = y + row * Dd;
#pragma unroll
    for (int i = 0; i < 8; i++) {
        int idx = threadIdx.x + (i << 8);
        yr[idx] = (v[i] - mu) * inv * w[idx] + b[idx];
    }
}

// ---------------- cos/sin of sheaf thetas ----------------
__global__ void sheaf_cs_kernel(const float* __restrict__ th,
                                float* __restrict__ c, float* __restrict__ s)
{
    int i = blockIdx.x * blockDim.x + threadIdx.x;
    if (i < 4 * DH) { float t = th[i]; c[i] = cosf(t); s[i] = sinf(t); }
}

// ---------------- sheaf: pre = xln - |alpha| * lap ----------------
// lap = 4*xln[t] - sum_idx rot_inv(xln[t+delta], c_idx, s_idx), delta = idx-3
__global__ void __launch_bounds__(256) sheaf_pre_kernel(const float* __restrict__ xln,
                                                        float* __restrict__ pre,
                                                        const float* __restrict__ cs,
                                                        const float* __restrict__ sn,
                                                        const float* __restrict__ alpha_p)
{
    int row = blockIdx.x;
    int b = row / Tt, t = row % Tt;
    float a = fabsf(alpha_p[0]);
    const float* xr = xln + (size_t)row * Dd;
    float* pr = pre + (size_t)row * Dd;
#pragma unroll
    for (int ii = 0; ii < 4; ii++) {
        int j = threadIdx.x + (ii << 8);
        float xre = xr[j], xim = xr[j + DH];
        float lr = 4.f * xre, li = 4.f * xim;
#pragma unroll
        for (int idx = 0; idx < 4; idx++) {
            int tn = t + (idx - 3);
            float yr = 0.f, yi = 0.f;
            if (tn >= 0) {
                const float* y = xln + ((size_t)b * Tt + tn) * Dd;
                yr = y[j]; yi = y[j + DH];
            }
            float c = cs[idx * DH + j], ss = sn[idx * DH + j];
            lr -= yr * c + yi * ss;          // rot_inv real part
            li -= yi * c - yr * ss;          // rot_inv imag part
        }
        pr[j]      = xre - a * lr;
        pr[j + DH] = xim - a * li;
    }
}

// ---------------- gist angle cos/sin per (batch, dh) ----------------
__global__ void gist_cs_kernel(const float* __restrict__ gt,   // [B,K,DH]
                               const float* __restrict__ gm,   // [B,K]
                               const float* __restrict__ gw,   // [B,K]
                               const float* __restrict__ strength,
                               float* __restrict__ c, float* __restrict__ s)
{
    int i = blockIdx.x * blockDim.x + threadIdx.x;
    if (i >= Bb * DH) return;
    int b = i / DH, j = i % DH;
    float sig = 1.f / (1.f + expf(-strength[0]));
    float wsum = 0.f, th = 0.f;
#pragma unroll
    for (int k = 0; k < KK; k++) {
        float w = gw[b * KK + k] * gm[b * KK + k];
        wsum += w;
        th += w * gt[(size_t)(b * KK + k) * DH + j];
    }
    th = th / (wsum + 1e-8f) * sig;
    c[i] = cosf(th); s[i] = sinf(th);
}

// ---------------- fused: xn=LN(x); rot=rotate(xn); x += LN(rot) - xn (in place) ----------------
__global__ void __launch_bounds__(256) gist_fused_kernel(float* __restrict__ x,
    const float* __restrict__ lnw, const float* __restrict__ lnb,
    const float* __restrict__ grw, const float* __restrict__ grb,
    const float* __restrict__ gc, const float* __restrict__ gs)
{
    __shared__ float sh[32];
    size_t row = blockIdx.x;
    int b = blockIdx.x / Tt;
    float* xr = x + row * Dd;
    float v[8]; float s = 0.f, s2 = 0.f;
#pragma unroll
    for (int i = 0; i < 8; i++) {
        v[i] = xr[threadIdx.x + (i << 8)];
        s += v[i]; s2 += v[i] * v[i];
    }
    block_reduce2(s, s2, sh);
    float mu = s * (1.f / Dd);
    float inv = rsqrtf(s2 * (1.f / Dd) - mu * mu + 1e-5f);
    float xn[8];
#pragma unroll
    for (int i = 0; i < 8; i++) {
        int idx = threadIdx.x + (i << 8);
        xn[i] = (v[i] - mu) * inv * lnw[idx] + lnb[idx];
    }
    // rotation: element idx pairs with idx+DH; with stride-256 mapping those are i and i+4
    float rot[8]; float rs = 0.f, rs2 = 0.f;
#pragma unroll
    for (int i = 0; i < 4; i++) {
        int j = threadIdx.x + (i << 8);
        float c = gc[b * DH + j], sn = gs[b * DH + j];
        float r = xn[i], im = xn[i + 4];
        rot[i]     = r * c - im * sn;
        rot[i + 4] = r * sn + im * c;
    }
#pragma unroll
    for (int i = 0; i < 8; i++) { rs += rot[i]; rs2 += rot[i] * rot[i]; }
    block_reduce2(rs, rs2, sh);
    float mu2 = rs * (1.f / Dd);
    float inv2 = rsqrtf(rs2 * (1.f / Dd) - mu2 * mu2 + 1e-5f);
#pragma unroll
    for (int i = 0; i < 8; i++) {
        int idx = threadIdx.x + (i << 8);
        xr[idx] = v[i] + ((rot[i] - mu2) * inv2 * grw[idx] + grb[idx]) - xn[i];
    }
}

// ---------------- pack concat([gist_theta, gist_mag]) into [64, KPAD] ----------------
__global__ void pack_gist_in(const float* __restrict__ gt, const float* __restrict__ gm,
                             float* __restrict__ out)
{
    int i = blockIdx.x * blockDim.x + threadIdx.x;
    if (i >= 64 * KPAD) return;
    int r = i / KPAD, f = i % KPAD;
    float v = 0.f;
    if (f < DH) v = gt[(size_t)r * DH + f];
    else if (f == DH) v = gm[r];
    out[i] = v;
}

__global__ void pad_W_kernel(const float* __restrict__ W, float* __restrict__ out)
{
    int i = blockIdx.x * blockDim.x + threadIdx.x;
    if (i >= Dd * KPAD) return;
    int o = i / KPAD, f = i % KPAD;
    out[i] = (f < DH + 1) ? W[(size_t)o * (DH + 1) + f] : 0.f;
}

// ---------------- SGEMM: C[m,n] = sum_k A[m,k]*W[n,k] (+add1)(+add2)(+bias[n]) ----------------
// 128x128 tile, BK=8, 256 threads, 8x8 per thread, double-buffered smem.
// Requires Kd % 8 == 0 and N % 128 == 0; M arbitrary.
__global__ void __launch_bounds__(256) sgemm_nt(const float* __restrict__ A,
                                                const float* __restrict__ W,
                                                float* __restrict__ C,
                                                const float* __restrict__ add1,
                                                const float* __restrict__ add2,
                                                const float* __restrict__ bias,
                                                int M, int N, int Kd)
{
    __shared__ float As[2][8][128];
    __shared__ float Bs[2][8][128];
    const int tid = threadIdx.x;
    const int bm = blockIdx.y * 128;
    const int bn = blockIdx.x * 128;
    const int lrow = tid >> 1;
    const int lcol = (tid & 1) << 2;
    const int tx = tid & 15;
    const int ty = tid >> 4;
    const int tm0 = ty * 8, tn0 = tx * 8;

    const float* Aptr = A + (size_t)(bm + lrow) * Kd + lcol;
    const float* Wptr = W + (size_t)(bn + lrow) * Kd + lcol;
    const bool a_ok = (bm + lrow) < M;

    float acc[8][8];
#pragma unroll
    for (int i = 0; i < 8; i++)
#pragma unroll
        for (int j = 0; j < 8; j++) acc[i][j] = 0.f;

    float4 pa = a_ok ? *(const float4*)Aptr : make_float4(0.f, 0.f, 0.f, 0.f);
    float4 pb = *(const float4*)Wptr;
    As[0][lcol + 0][lrow] = pa.x; As[0][lcol + 1][lrow] = pa.y;
    As[0][lcol + 2][lrow] = pa.z; As[0][lcol + 3][lrow] = pa.w;
    Bs[0][lcol + 0][lrow] = pb.x; Bs[0][lcol + 1][lrow] = pb.y;
    Bs[0][lcol + 2][lrow] = pb.z; Bs[0][lcol + 3][lrow] = pb.w;
    __syncthreads();

    const int ntiles = Kd >> 3;
    for (int kt = 0; kt < ntiles; kt++) {
        int buf = kt & 1;
        if (kt + 1 < ntiles) {
            pa = a_ok ? *(const float4*)(Aptr + (size_t)(kt + 1) * 8)
                      : make_float4(0.f, 0.f, 0.f, 0.f);
            pb = *(const float4*)(Wptr + (size_t)(kt + 1) * 8);
        }
#pragma unroll
        for (int k = 0; k < 8; k++) {
            float4 a0 = *(const float4*)&As[buf][k][tm0];
            float4 a1 = *(const float4*)&As[buf][k][tm0 + 4];
            float4 b0 = *(const float4*)&Bs[buf][k][tn0];
            float4 b1 = *(const float4*)&Bs[buf][k][tn0 + 4];
            float af[8] = {a0.x, a0.y, a0.z, a0.w, a1.x, a1.y, a1.z, a1.w};
            float bf[8] = {b0.x, b0.y, b0.z, b0.w, b1.x, b1.y, b1.z, b1.w};
#pragma unroll
            for (int i = 0; i < 8; i++)
#pragma unroll
                for (int j = 0; j < 8; j++)
                    acc[i][j] += af[i] * bf[j];
        }
        if (kt + 1 < ntiles) {
            int nb = buf ^ 1;
            As[nb][lcol + 0][lrow] = pa.x; As[nb][lcol + 1][lrow] = pa.y;
            As[nb][lcol + 2][lrow] = pa.z; As[nb][lcol + 3][lrow] = pa.w;
            Bs[nb][lcol + 0][lrow] = pb.x; Bs[nb][lcol + 1][lrow] = pb.y;
            Bs[nb][lcol + 2][lrow] = pb.z; Bs[nb][lcol + 3][lrow] = pb.w;
            __syncthreads();
        }
    }

#pragma unroll
    for (int i = 0; i < 8; i++) {
        int gm = bm + tm0 + i;
        if (gm < M) {
            size_t rowoff = (size_t)gm * N;
#pragma unroll
            for (int j = 0; j < 8; j += 4) {
                int gn = bn + tn0 + j;
                float4 v = make_float4(acc[i][j], acc[i][j + 1], acc[i][j + 2], acc[i][j + 3]);
                if (add1) {
                    float4 t = *(const float4*)(add1 + rowoff + gn);
                    v.x += t.x; v.y += t.y; v.z += t.z; v.w += t.w;
                }
                if (add2) {
                    float4 t = *(const float4*)(add2 + rowoff + gn);
                    v.x += t.x; v.y += t.y; v.z += t.z; v.w += t.w;
                }
                if (bias) {
                    float4 t = *(const float4*)(bias + gn);
                    v.x += t.x; v.y += t.y; v.z += t.z; v.w += t.w;
                }
                *(float4*)(C + rowoff + gn) = v;
            }
        }
    }
}

// ---------------- tiny cross-attention: 16 keys per (b,h), warp per (t,h) ----------------
__global__ void __launch_bounds__(256) attn_kernel(const float* __restrict__ Q,
                                                   const float* __restrict__ Kh,
                                                   const float* __restrict__ Vv,
                                                   float* __restrict__ ctx)
{
    __shared__ float ks[KK][HD];
    __shared__ float vs[KK][HD];
    int bh = blockIdx.y;
    int b = bh >> 4, h = bh & 15;
    for (int i = threadIdx.x; i < KK * HD; i += 256) {
        int k = i >> 7, dd = i & 127;
        size_t off = ((size_t)(b * KK + k)) * Dd + h * HD + dd;
        ks[k][dd] = Kh[off];
        vs[k][dd] = Vv[off];
    }
    __syncthreads();
    int warp = threadIdx.x >> 5, lane = threadIdx.x & 31;
    int t = blockIdx.x * 8 + warp;
    size_t qoff = ((size_t)(b * Tt + t)) * Dd + h * HD + lane * 4;
    float4 q = *(const float4*)(Q + qoff);
    float sc[KK];
#pragma unroll
    for (int k = 0; k < KK; k++) {
        float4 kv = *(const float4*)&ks[k][lane * 4];
        float d = q.x * kv.x + q.y * kv.y + q.z * kv.z + q.w * kv.w;
#pragma unroll
        for (int o = 16; o > 0; o >>= 1) d += __shfl_xor_sync(0xffffffffu, d, o);
        sc[k] = d * 0.088388347648318447f;   // 1/sqrt(128)
    }
    float m = sc[0];
#pragma unroll
    for (int k = 1; k < KK; k++) m = fmaxf(m, sc[k]);
    float ssum = 0.f;
#pragma unroll
    for (int k = 0; k < KK; k++) { sc[k] = expf(sc[k] - m); ssum += sc[k]; }
    float rinv = 1.f / ssum;
    float4 o = make_float4(0.f, 0.f, 0.f, 0.f);
#pragma unroll
    for (int k = 0; k < KK; k++) {
        float p = sc[k] * rinv;
        float4 vv = *(const float4*)&vs[k][lane * 4];
        o.x += p * vv.x; o.y += p * vv.y; o.z += p * vv.z; o.w += p * vv.w;
    }
    *(float4*)(ctx + qoff) = o;
}

// ---------------- orchestration ----------------
extern "C" void kernel_launch(void* const* d_in, const int* in_sizes, int n_in,
                              void* d_out, int out_size)
{
    const float* x            = (const float*)d_in[0];
    const float* gist_theta   = (const float*)d_in[1];
    const float* gist_mag     = (const float*)d_in[2];
    const float* gist_weights = (const float*)d_in[3];
    const float* ln_sheaf_w   = (const float*)d_in[4];
    const float* ln_sheaf_b   = (const float*)d_in[5];
    const float* sheaf_thetas = (const float*)d_in[6];
    const float* alpha        = (const float*)d_in[7];
    const float* corr_W       = (const float*)d_in[8];
    const float* ln_gist_w    = (const float*)d_in[9];
    const float* ln_gist_b    = (const float*)d_in[10];
    const float* gist_strength= (const float*)d_in[11];
    const float* gr_ln_w      = (const float*)d_in[12];
    const float* gr_ln_b      = (const float*)d_in[13];
    const float* ln_gca_w     = (const float*)d_in[14];
    const float* ln_gca_b     = (const float*)d_in[15];
    const float* Wq           = (const float*)d_in[16];
    const float* Wk           = (const float*)d_in[17];
    const float* Wv           = (const float*)d_in[18];
    const float* Wo           = (const float*)d_in[19];
    const float* gist_up_W    = (const float*)d_in[20];
    const float* gist_up_b    = (const float*)d_in[21];
    float* out = (float*)d_out;

    float *S0, *S1, *repr, *Khb, *Vb, *packin, *Wpad, *shc, *shs, *gc, *gs;
    cudaGetSymbolAddress((void**)&S0, g_S0);
    cudaGetSymbolAddress((void**)&S1, g_S1);
    cudaGetSymbolAddress((void**)&repr, g_repr);
    cudaGetSymbolAddress((void**)&Khb, g_Kh);
    cudaGetSymbolAddress((void**)&Vb, g_Vv);
    cudaGetSymbolAddress((void**)&packin, g_packin);
    cudaGetSymbolAddress((void**)&Wpad, g_Wpad);
    cudaGetSymbolAddress((void**)&shc, g_shc);
    cudaGetSymbolAddress((void**)&shs, g_shs);
    cudaGetSymbolAddress((void**)&gc, g_gc);
    cudaGetSymbolAddress((void**)&gs, g_gs);

    dim3 gemm_big(Dd / 128, BT / 128);   // (16, 64)
    dim3 gemm_small(Dd / 128, 1);        // M = 64

    // ---- stage 1: sheaf ----
    ln_kernel<<<BT, 256>>>(x, S0, ln_sheaf_w, ln_sheaf_b);
    sheaf_cs_kernel<<<(4 * DH + 255) / 256, 256>>>(sheaf_thetas, shc, shs);
    sheaf_pre_kernel<<<BT, 256>>>(S0, S1, shc, shs, alpha);
    // out = x + pre + pre @ corr_W^T
    sgemm_nt<<<gemm_big, 256>>>(S1, corr_W, out, x, S1, nullptr, BT, Dd, Dd);

    // ---- stage 2: gist rotation (fused LN -> rotate -> LN -> residual, in place) ----
    gist_cs_kernel<<<(Bb * DH + 255) / 256, 256>>>(gist_theta, gist_mag, gist_weights,
                                                   gist_strength, gc, gs);
    gist_fused_kernel<<<BT, 256>>>(out, ln_gist_w, ln_gist_b, gr_ln_w, gr_ln_b, gc, gs);

    // ---- stage 3: gist cross-attention ----
    pack_gist_in<<<(64 * KPAD + 255) / 256, 256>>>(gist_theta, gist_mag, packin);
    pad_W_kernel<<<(Dd * KPAD + 255) / 256, 256>>>(gist_up_W, Wpad);
    // gist_repr = packin @ Wpad^T + bias
    sgemm_nt<<<gemm_small, 256>>>(packin, Wpad, repr, nullptr, nullptr, gist_up_b,
                                  64, Dd, KPAD);
    sgemm_nt<<<gemm_small, 256>>>(repr, Wk, Khb, nullptr, nullptr, nullptr, 64, Dd, Dd);
    sgemm_nt<<<gemm_small, 256>>>(repr, Wv, Vb, nullptr, nullptr, nullptr, 64, Dd, Dd);
    ln_kernel<<<BT, 256>>>(out, S0, ln_gca_w, ln_gca_b);
    sgemm_nt<<<gemm_big, 256>>>(S0, Wq, S1, nullptr, nullptr, nullptr, BT, Dd, Dd); // Q
    attn_kernel<<<dim3(Tt / 8, Bb * NH), 256>>>(S1, Khb, Vb, S0);                   // ctx
    // out += ctx @ Wo^T
    sgemm_nt<<<gemm_big, 256>>>(S0, Wo, out, out, nullptr, nullptr, BT, Dd, Dd);
}

// round 5
// speedup vs baseline: 2.9648x; 2.9648x over previous
#include <cuda_runtime.h>
#include <math.h>
#include <stdint.h>

// Problem constants
#define Bb 4
#define Tt 2048
#define Dd 2048
#define DH 1024
#define KK 16
#define NH 16
#define HD 128
#define BT (Bb*Tt)          // 8192 rows
#define KPAD 1032           // dh+1 padded to multiple of 8

// ---------------- scratch (device globals; no allocation) ----------------
__device__ float g_S0[(size_t)BT * Dd];     // ln outputs / ctx
__device__ float g_S1[(size_t)BT * Dd];     // sheaf pre / Q
__device__ float g_Wr[3ull * Dd * Dd];      // tf32-rounded corr_W / Wq / Wo
__device__ float g_repr[64 * Dd];           // gist_repr
__device__ float g_Kh[64 * Dd];
__device__ float g_Vv[64 * Dd];
__device__ float g_packin[64 * KPAD];
__device__ float g_Wpad[Dd * KPAD];
__device__ float g_shc[4 * DH];
__device__ float g_shs[4 * DH];
__device__ float g_gc[Bb * DH];
__device__ float g_gs[Bb * DH];

// ---------------- helpers ----------------
__device__ __forceinline__ uint32_t smem_u32(const void* p) {
    uint32_t a;
    asm("{ .reg .u64 t; cvta.to.shared.u64 t, %1; cvt.u32.u64 %0, t; }" : "=r"(a) : "l"(p));
    return a;
}
__device__ __forceinline__ float rtf(float x) {   // round-to-nearest tf32
    uint32_t u;
    asm("cvt.rna.tf32.f32 %0, %1;" : "=r"(u) : "f"(x));
    return __uint_as_float(u);
}
__device__ __forceinline__ void cp16(uint32_t dst, const void* src) {
    asm volatile("cp.async.cg.shared.global [%0], [%1], 16;" :: "r"(dst), "l"(src));
}
__device__ __forceinline__ void mma_tf32_16n8k8(float& c0, float& c1, float& c2, float& c3,
                                                uint32_t a0, uint32_t a1, uint32_t a2, uint32_t a3,
                                                uint32_t b0, uint32_t b1) {
    asm volatile(
        "mma.sync.aligned.m16n8k8.row.col.f32.tf32.tf32.f32 "
        "{%0,%1,%2,%3}, {%4,%5,%6,%7}, {%8,%9}, {%0,%1,%2,%3};"
        : "+f"(c0), "+f"(c1), "+f"(c2), "+f"(c3)
        : "r"(a0), "r"(a1), "r"(a2), "r"(a3), "r"(b0), "r"(b1));
}

// ============== tf32 warp-MMA NT GEMM: C = A @ W^T (+add1)(+add2) ==============
// A: [M,K] row-major, W: [N,K] row-major, operands pre-rounded to tf32.
// M%128==0, N%128==0, K%32==0. 256 threads, 128x128 tile, K-chunk 32, 2-stage cp.async.
// SMEM stage layout: As[128 rows][36 floats] then Bs[128 rows][36 floats] (pad 4).
#define KC 32
#define ROWP 36
#define A_BYTES (128 * ROWP * 4)          // 18432
#define STAGE_BYTES (2 * A_BYTES)          // 36864
#define GEMM_MMA_SMEM (2 * STAGE_BYTES)    // 73728

__global__ void __launch_bounds__(256) gemm_mma(const float* __restrict__ A,
                                                const float* __restrict__ W,
                                                float* __restrict__ C,
                                                const float* __restrict__ add1,
                                                const float* __restrict__ add2,
                                                int M, int N, int K)
{
    extern __shared__ char dyn[];
    const int tid = threadIdx.x;
    const int bm = blockIdx.y * 128;
    const int bn = blockIdx.x * 128;
    const int nt = K >> 5;

    const int lane = tid & 31, wid = tid >> 5;
    const int wm = wid & 1, wn = wid >> 1;      // warp tile: 64 (m) x 32 (n)
    const int gid = lane >> 2, tig = lane & 3;
    const int am0 = wm * 64;
    const int bn0 = wn * 32;

    const uint32_t tile0 = smem_u32(dyn);
    const float* Abase = A + (size_t)bm * K;
    const float* Wbase = W + (size_t)bn * K;

    float acc[4][4][4];
#pragma unroll
    for (int i = 0; i < 4; i++)
#pragma unroll
        for (int j = 0; j < 4; j++)
#pragma unroll
            for (int r = 0; r < 4; r++) acc[i][j][r] = 0.f;

    auto load_stage = [&](int kt) {
        uint32_t base = tile0 + (kt & 1) * STAGE_BYTES;
#pragma unroll
        for (int i = 0; i < 4; i++) {
            int c = i * 256 + tid;              // 0..1023
            int row = c >> 3, ch = c & 7;
            uint32_t dof = (uint32_t)(row * (ROWP * 4) + ch * 16);
            cp16(base + dof,           Abase + (size_t)row * K + kt * KC + ch * 4);
            cp16(base + A_BYTES + dof, Wbase + (size_t)row * K + kt * KC + ch * 4);
        }
        asm volatile("cp.async.commit_group;" ::: "memory");
    };

    load_stage(0);

    for (int kt = 0; kt < nt; kt++) {
        if (kt + 1 < nt) {
            load_stage(kt + 1);
            asm volatile("cp.async.wait_group 1;" ::: "memory");
        } else {
            asm volatile("cp.async.wait_group 0;" ::: "memory");
        }
        __syncthreads();

        const float* As = (const float*)(dyn + (kt & 1) * STAGE_BYTES);
        const float* Bs = (const float*)(dyn + (kt & 1) * STAGE_BYTES + A_BYTES);
#pragma unroll
        for (int ks = 0; ks < 4; ks++) {
            const int k0 = ks * 8;
            uint32_t a[4][4], b[4][2];
#pragma unroll
            for (int mf = 0; mf < 4; mf++) {
                const float* ar = As + (am0 + mf * 16 + gid) * ROWP + k0 + tig;
                a[mf][0] = __float_as_uint(ar[0]);
                a[mf][1] = __float_as_uint(ar[8 * ROWP]);
                a[mf][2] = __float_as_uint(ar[4]);
                a[mf][3] = __float_as_uint(ar[8 * ROWP + 4]);
            }
#pragma unroll
            for (int nf = 0; nf < 4; nf++) {
                const float* br = Bs + (bn0 + nf * 8 + gid) * ROWP + k0 + tig;
                b[nf][0] = __float_as_uint(br[0]);
                b[nf][1] = __float_as_uint(br[4]);
            }
#pragma unroll
            for (int mf = 0; mf < 4; mf++)
#pragma unroll
                for (int nf = 0; nf < 4; nf++)
                    mma_tf32_16n8k8(acc[mf][nf][0], acc[mf][nf][1],
                                    acc[mf][nf][2], acc[mf][nf][3],
                                    a[mf][0], a[mf][1], a[mf][2], a[mf][3],
                                    b[nf][0], b[nf][1]);
        }
        __syncthreads();
    }

    // epilogue: float2 stores with fused residual adds
#pragma unroll
    for (int mf = 0; mf < 4; mf++) {
        int row0 = bm + am0 + mf * 16 + gid;
        size_t ro0 = (size_t)row0 * N;
        size_t ro1 = ro0 + (size_t)8 * N;
#pragma unroll
        for (int nf = 0; nf < 4; nf++) {
            int col = bn + bn0 + nf * 8 + tig * 2;
            float2 v0 = make_float2(acc[mf][nf][0], acc[mf][nf][1]);
            float2 v1 = make_float2(acc[mf][nf][2], acc[mf][nf][3]);
            if (add1) {
                float2 t0 = *(const float2*)(add1 + ro0 + col);
                float2 t1 = *(const float2*)(add1 + ro1 + col);
                v0.x += t0.x; v0.y += t0.y; v1.x += t1.x; v1.y += t1.y;
            }
            if (add2) {
                float2 t0 = *(const float2*)(add2 + ro0 + col);
                float2 t1 = *(const float2*)(add2 + ro1 + col);
                v0.x += t0.x; v0.y += t0.y; v1.x += t1.x; v1.y += t1.y;
            }
            *(float2*)(C + ro0 + col) = v0;
            *(float2*)(C + ro1 + col) = v1;
        }
    }
}

// ---------------- round a weight matrix to tf32 (rna) ----------------
__global__ void round_w(const float* __restrict__ in, float* __restrict__ out, int n4)
{
    int i = blockIdx.x * blockDim.x + threadIdx.x;
    if (i >= n4) return;
    float4 v = ((const float4*)in)[i];
    v.x = rtf(v.x); v.y = rtf(v.y); v.z = rtf(v.z); v.w = rtf(v.w);
    ((float4*)out)[i] = v;
}

// ---------------- block reduction (sum of two values) ----------------
__device__ __forceinline__ void block_reduce2(float& a, float& b, float* sh)
{
    __syncthreads();
#pragma unroll
    for (int o = 16; o > 0; o >>= 1) {
        a += __shfl_xor_sync(0xffffffffu, a, o);
        b += __shfl_xor_sync(0xffffffffu, b, o);
    }
    int warp = threadIdx.x >> 5, lane = threadIdx.x & 31;
    if (lane == 0) { sh[warp] = a; sh[8 + warp] = b; }
    __syncthreads();
    if (threadIdx.x < 32) {
        float aa = (lane < 8) ? sh[lane] : 0.f;
        float bb = (lane < 8) ? sh[8 + lane] : 0.f;
#pragma unroll
        for (int o = 4; o > 0; o >>= 1) {
            aa += __shfl_xor_sync(0xffffffffu, aa, o);
            bb += __shfl_xor_sync(0xffffffffu, bb, o);
        }
        if (lane == 0) { sh[16] = aa; sh[17] = bb; }
    }
    __syncthreads();
    a = sh[16]; b = sh[17];
}

// ---------------- LayerNorm (optionally tf32-round the store) ----------------
__global__ void __launch_bounds__(256) ln_kernel(const float* __restrict__ x,
                                                 float* __restrict__ y,
                                                 const float* __restrict__ w,
                                                 const float* __restrict__ b,
                                                 int round_out)
{
    __shared__ float sh[32];
    size_t row = blockIdx.x;
    const float* xr = x + row * Dd;
    float v[8]; float s = 0.f, s2 = 0.f;
#pragma unroll
    for (int i = 0; i < 8; i++) {
        v[i] = xr[threadIdx.x + (i << 8)];
        s += v[i]; s2 += v[i] * v[i];
    }
    block_reduce2(s, s2, sh);
    float mu = s * (1.f / Dd);
    float inv = rsqrtf(s2 * (1.f / Dd) - mu * mu + 1e-5f);
    float* yr = y + row * Dd;
#pragma unroll
    for (int i = 0; i < 8; i++) {
        int idx = threadIdx.x + (i << 8);
        float o = (v[i] - mu) * inv * w[idx] + b[idx];
        yr[idx] = round_out ? rtf(o) : o;
    }
}

// ---------------- cos/sin of sheaf thetas ----------------
__global__ void sheaf_cs_kernel(const float* __restrict__ th,
                                float* __restrict__ c, float* __restrict__ s)
{
    int i = blockIdx.x * blockDim.x + threadIdx.x;
    if (i < 4 * DH) { float t = th[i]; c[i] = cosf(t); s[i] = sinf(t); }
}

// ---------------- sheaf: pre = xln - |alpha| * lap (tf32-rounded) ----------------
__global__ void __launch_bounds__(256) sheaf_pre_kernel(const float* __restrict__ xln,
                                                        float* __restrict__ pre,
                                                        const float* __restrict__ cs,
                                                        const float* __restrict__ sn,
                                                        const float* __restrict__ alpha_p)
{
    int row = blockIdx.x;
    int b = row / Tt, t = row % Tt;
    float a = fabsf(alpha_p[0]);
    const float* xr = xln + (size_t)row * Dd;
    float* pr = pre + (size_t)row * Dd;
#pragma unroll
    for (int ii = 0; ii < 4; ii++) {
        int j = threadIdx.x + (ii << 8);
        float xre = xr[j], xim = xr[j + DH];
        float lr = 4.f * xre, li = 4.f * xim;
#pragma unroll
        for (int idx = 0; idx < 4; idx++) {
            int tn = t + (idx - 3);
            float yr = 0.f, yi = 0.f;
            if (tn >= 0) {
                const float* y = xln + ((size_t)b * Tt + tn) * Dd;
                yr = y[j]; yi = y[j + DH];
            }
            float c = cs[idx * DH + j], ss = sn[idx * DH + j];
            lr -= yr * c + yi * ss;
            li -= yi * c - yr * ss;
        }
        pr[j]      = rtf(xre - a * lr);
        pr[j + DH] = rtf(xim - a * li);
    }
}

// ---------------- gist angle cos/sin per (batch, dh) ----------------
__global__ void gist_cs_kernel(const float* __restrict__ gt,
                               const float* __restrict__ gm,
                               const float* __restrict__ gw,
                               const float* __restrict__ strength,
                               float* __restrict__ c, float* __restrict__ s)
{
    int i = blockIdx.x * blockDim.x + threadIdx.x;
    if (i >= Bb * DH) return;
    int b = i / DH, j = i % DH;
    float sig = 1.f / (1.f + expf(-strength[0]));
    float wsum = 0.f, th = 0.f;
#pragma unroll
    for (int k = 0; k < KK; k++) {
        float w = gw[b * KK + k] * gm[b * KK + k];
        wsum += w;
        th += w * gt[(size_t)(b * KK + k) * DH + j];
    }
    th = th / (wsum + 1e-8f) * sig;
    c[i] = cosf(th); s[i] = sinf(th);
}

// ---------------- fused: xn=LN(x); rot=rotate(xn); x += LN(rot) - xn ----------------
__global__ void __launch_bounds__(256) gist_fused_kernel(float* __restrict__ x,
    const float* __restrict__ lnw, const float* __restrict__ lnb,
    const float* __restrict__ grw, const float* __restrict__ grb,
    const float* __restrict__ gc, const float* __restrict__ gs)
{
    __shared__ float sh[32];
    size_t row = blockIdx.x;
    int b = blockIdx.x / Tt;
    float* xr = x + row * Dd;
    float v[8]; float s = 0.f, s2 = 0.f;
#pragma unroll
    for (int i = 0; i < 8; i++) {
        v[i] = xr[threadIdx.x + (i << 8)];
        s += v[i]; s2 += v[i] * v[i];
    }
    block_reduce2(s, s2, sh);
    float mu = s * (1.f / Dd);
    float inv = rsqrtf(s2 * (1.f / Dd) - mu * mu + 1e-5f);
    float xn[8];
#pragma unroll
    for (int i = 0; i < 8; i++) {
        int idx = threadIdx.x + (i << 8);
        xn[i] = (v[i] - mu) * inv * lnw[idx] + lnb[idx];
    }
    float rot[8]; float rs = 0.f, rs2 = 0.f;
#pragma unroll
    for (int i = 0; i < 4; i++) {
        int j = threadIdx.x + (i << 8);
        float c = gc[b * DH + j], sn = gs[b * DH + j];
        float r = xn[i], im = xn[i + 4];
        rot[i]     = r * c - im * sn;
        rot[i + 4] = r * sn + im * c;
    }
#pragma unroll
    for (int i = 0; i < 8; i++) { rs += rot[i]; rs2 += rot[i] * rot[i]; }
    block_reduce2(rs, rs2, sh);
    float mu2 = rs * (1.f / Dd);
    float inv2 = rsqrtf(rs2 * (1.f / Dd) - mu2 * mu2 + 1e-5f);
#pragma unroll
    for (int i = 0; i < 8; i++) {
        int idx = threadIdx.x + (i << 8);
        xr[idx] = v[i] + ((rot[i] - mu2) * inv2 * grw[idx] + grb[idx]) - xn[i];
    }
}

// ---------------- pack concat([gist_theta, gist_mag]) into [64, KPAD] ----------------
__global__ void pack_gist_in(const float* __restrict__ gt, const float* __restrict__ gm,
                             float* __restrict__ out)
{
    int i = blockIdx.x * blockDim.x + threadIdx.x;
    if (i >= 64 * KPAD) return;
    int r = i / KPAD, f = i % KPAD;
    float v = 0.f;
    if (f < DH) v = gt[(size_t)r * DH + f];
    else if (f == DH) v = gm[r];
    out[i] = v;
}

__global__ void pad_W_kernel(const float* __restrict__ W, float* __restrict__ out)
{
    int i = blockIdx.x * blockDim.x + threadIdx.x;
    if (i >= Dd * KPAD) return;
    int o = i / KPAD, f = i % KPAD;
    out[i] = (f < DH + 1) ? W[(size_t)o * (DH + 1) + f] : 0.f;
}

// ---------------- SIMT SGEMM (small M=64 GEMMs only) ----------------
__global__ void __launch_bounds__(256) sgemm_nt(const float* __restrict__ A,
                                                const float* __restrict__ W,
                                                float* __restrict__ C,
                                                const float* __restrict__ add1,
                                                const float* __restrict__ add2,
                                                const float* __restrict__ bias,
                                                int M, int N, int Kd)
{
    __shared__ float As[2][8][128];
    __shared__ float Bs[2][8][128];
    const int tid = threadIdx.x;
    const int bm = blockIdx.y * 128;
    const int bn = blockIdx.x * 128;
    const int lrow = tid >> 1;
    const int lcol = (tid & 1) << 2;
    const int tx = tid & 15;
    const int ty = tid >> 4;
    const int tm0 = ty * 8, tn0 = tx * 8;

    const float* Aptr = A + (size_t)(bm + lrow) * Kd + lcol;
    const float* Wptr = W + (size_t)(bn + lrow) * Kd + lcol;
    const bool a_ok = (bm + lrow) < M;

    float acc[8][8];
#pragma unroll
    for (int i = 0; i < 8; i++)
#pragma unroll
        for (int j = 0; j < 8; j++) acc[i][j] = 0.f;

    float4 pa = a_ok ? *(const float4*)Aptr : make_float4(0.f, 0.f, 0.f, 0.f);
    float4 pb = *(const float4*)Wptr;
    As[0][lcol + 0][lrow] = pa.x; As[0][lcol + 1][lrow] = pa.y;
    As[0][lcol + 2][lrow] = pa.z; As[0][lcol + 3][lrow] = pa.w;
    Bs[0][lcol + 0][lrow] = pb.x; Bs[0][lcol + 1][lrow] = pb.y;
    Bs[0][lcol + 2][lrow] = pb.z; Bs[0][lcol + 3][lrow] = pb.w;
    __syncthreads();

    const int ntiles = Kd >> 3;
    for (int kt = 0; kt < ntiles; kt++) {
        int buf = kt & 1;
        if (kt + 1 < ntiles) {
            pa = a_ok ? *(const float4*)(Aptr + (size_t)(kt + 1) * 8)
                      : make_float4(0.f, 0.f, 0.f, 0.f);
            pb = *(const float4*)(Wptr + (size_t)(kt + 1) * 8);
        }
#pragma unroll
        for (int k = 0; k < 8; k++) {
            float4 a0 = *(const float4*)&As[buf][k][tm0];
            float4 a1 = *(const float4*)&As[buf][k][tm0 + 4];
            float4 b0 = *(const float4*)&Bs[buf][k][tn0];
            float4 b1 = *(const float4*)&Bs[buf][k][tn0 + 4];
            float af[8] = {a0.x, a0.y, a0.z, a0.w, a1.x, a1.y, a1.z, a1.w};
            float bf[8] = {b0.x, b0.y, b0.z, b0.w, b1.x, b1.y, b1.z, b1.w};
#pragma unroll
            for (int i = 0; i < 8; i++)
#pragma unroll
                for (int j = 0; j < 8; j++)
                    acc[i][j] += af[i] * bf[j];
        }
        if (kt + 1 < ntiles) {
            int nb = buf ^ 1;
            As[nb][lcol + 0][lrow] = pa.x; As[nb][lcol + 1][lrow] = pa.y;
            As[nb][lcol + 2][lrow] = pa.z; As[nb][lcol + 3][lrow] = pa.w;
            Bs[nb][lcol + 0][lrow] = pb.x; Bs[nb][lcol + 1][lrow] = pb.y;
            Bs[nb][lcol + 2][lrow] = pb.z; Bs[nb][lcol + 3][lrow] = pb.w;
            __syncthreads();
        }
    }

#pragma unroll
    for (int i = 0; i < 8; i++) {
        int gm = bm + tm0 + i;
        if (gm < M) {
            size_t rowoff = (size_t)gm * N;
#pragma unroll
            for (int j = 0; j < 8; j += 4) {
                int gn = bn + tn0 + j;
                float4 v = make_float4(acc[i][j], acc[i][j + 1], acc[i][j + 2], acc[i][j + 3]);
                if (add1) {
                    float4 t = *(const float4*)(add1 + rowoff + gn);
                    v.x += t.x; v.y += t.y; v.z += t.z; v.w += t.w;
                }
                if (add2) {
                    float4 t = *(const float4*)(add2 + rowoff + gn);
                    v.x += t.x; v.y += t.y; v.z += t.z; v.w += t.w;
                }
                if (bias) {
                    float4 t = *(const float4*)(bias + gn);
                    v.x += t.x; v.y += t.y; v.z += t.z; v.w += t.w;
                }
                *(float4*)(C + rowoff + gn) = v;
            }
        }
    }
}

// ---------------- tiny cross-attention (ctx tf32-rounded for Wo GEMM) ----------------
__global__ void __launch_bounds__(256) attn_kernel(const float* __restrict__ Q,
                                                   const float* __restrict__ Kh,
                                                   const float* __restrict__ Vv,
                                                   float* __restrict__ ctx)
{
    __shared__ float ks[KK][HD];
    __shared__ float vs[KK][HD];
    int bh = blockIdx.y;
    int b = bh >> 4, h = bh & 15;
    for (int i = threadIdx.x; i < KK * HD; i += 256) {
        int k = i >> 7, dd = i & 127;
        size_t off = ((size_t)(b * KK + k)) * Dd + h * HD + dd;
        ks[k][dd] = Kh[off];
        vs[k][dd] = Vv[off];
    }
    __syncthreads();
    int warp = threadIdx.x >> 5, lane = threadIdx.x & 31;
    int t = blockIdx.x * 8 + warp;
    size_t qoff = ((size_t)(b * Tt + t)) * Dd + h * HD + lane * 4;
    float4 q = *(const float4*)(Q + qoff);
    float sc[KK];
#pragma unroll
    for (int k = 0; k < KK; k++) {
        float4 kv = *(const float4*)&ks[k][lane * 4];
        float d = q.x * kv.x + q.y * kv.y + q.z * kv.z + q.w * kv.w;
#pragma unroll
        for (int o = 16; o > 0; o >>= 1) d += __shfl_xor_sync(0xffffffffu, d, o);
        sc[k] = d * 0.088388347648318447f;
    }
    float m = sc[0];
#pragma unroll
    for (int k = 1; k < KK; k++) m = fmaxf(m, sc[k]);
    float ssum = 0.f;
#pragma unroll
    for (int k = 0; k < KK; k++) { sc[k] = expf(sc[k] - m); ssum += sc[k]; }
    float rinv = 1.f / ssum;
    float4 o = make_float4(0.f, 0.f, 0.f, 0.f);
#pragma unroll
    for (int k = 0; k < KK; k++) {
        float p = sc[k] * rinv;
        float4 vv = *(const float4*)&vs[k][lane * 4];
        o.x += p * vv.x; o.y += p * vv.y; o.z += p * vv.z; o.w += p * vv.w;
    }
    o.x = rtf(o.x); o.y = rtf(o.y); o.z = rtf(o.z); o.w = rtf(o.w);
    *(float4*)(ctx + qoff) = o;
}

// ---------------- orchestration ----------------
extern "C" void kernel_launch(void* const* d_in, const int* in_sizes, int n_in,
                              void* d_out, int out_size)
{
    const float* x            = (const float*)d_in[0];
    const float* gist_theta   = (const float*)d_in[1];
    const float* gist_mag     = (const float*)d_in[2];
    const float* gist_weights = (const float*)d_in[3];
    const float* ln_sheaf_w   = (const float*)d_in[4];
    const float* ln_sheaf_b   = (const float*)d_in[5];
    const float* sheaf_thetas = (const float*)d_in[6];
    const float* alpha        = (const float*)d_in[7];
    const float* corr_W       = (const float*)d_in[8];
    const float* ln_gist_w    = (const float*)d_in[9];
    const float* ln_gist_b    = (const float*)d_in[10];
    const float* gist_strength= (const float*)d_in[11];
    const float* gr_ln_w      = (const float*)d_in[12];
    const float* gr_ln_b      = (const float*)d_in[13];
    const float* ln_gca_w     = (const float*)d_in[14];
    const float* ln_gca_b     = (const float*)d_in[15];
    const float* Wq           = (const float*)d_in[16];
    const float* Wk           = (const float*)d_in[17];
    const float* Wv           = (const float*)d_in[18];
    const float* Wo           = (const float*)d_in[19];
    const float* gist_up_W    = (const float*)d_in[20];
    const float* gist_up_b    = (const float*)d_in[21];
    float* out = (float*)d_out;

    float *S0, *S1, *Wr, *repr, *Khb, *Vb, *packin, *Wpad, *shc, *shs, *gc, *gs;
    cudaGetSymbolAddress((void**)&S0, g_S0);
    cudaGetSymbolAddress((void**)&S1, g_S1);
    cudaGetSymbolAddress((void**)&Wr, g_Wr);
    cudaGetSymbolAddress((void**)&repr, g_repr);
    cudaGetSymbolAddress((void**)&Khb, g_Kh);
    cudaGetSymbolAddress((void**)&Vb, g_Vv);
    cudaGetSymbolAddress((void**)&packin, g_packin);
    cudaGetSymbolAddress((void**)&Wpad, g_Wpad);
    cudaGetSymbolAddress((void**)&shc, g_shc);
    cudaGetSymbolAddress((void**)&shs, g_shs);
    cudaGetSymbolAddress((void**)&gc, g_gc);
    cudaGetSymbolAddress((void**)&gs, g_gs);

    float* Wc = Wr;                        // rounded corr_W
    float* Wq_r = Wr + (size_t)Dd * Dd;    // rounded Wq
    float* Wo_r = Wr + 2ull * Dd * Dd;     // rounded Wo

    cudaFuncSetAttribute(gemm_mma, cudaFuncAttributeMaxDynamicSharedMemorySize,
                         GEMM_MMA_SMEM);

    dim3 gemm_big(Dd / 128, BT / 128);   // (16, 64)
    dim3 gemm_small(Dd / 128, 1);        // M = 64
    const int WN4 = Dd * Dd / 4;

    // ---- round GEMM weights to tf32 (upfront, independent) ----
    round_w<<<(WN4 + 255) / 256, 256>>>(corr_W, Wc, WN4);
    round_w<<<(WN4 + 255) / 256, 256>>>(Wq, Wq_r, WN4);
    round_w<<<(WN4 + 255) / 256, 256>>>(Wo, Wo_r, WN4);

    // ---- stage 1: sheaf ----
    ln_kernel<<<BT, 256>>>(x, S0, ln_sheaf_w, ln_sheaf_b, 0);
    sheaf_cs_kernel<<<(4 * DH + 255) / 256, 256>>>(sheaf_thetas, shc, shs);
    sheaf_pre_kernel<<<BT, 256>>>(S0, S1, shc, shs, alpha);
    // out = x + pre + pre @ corr_W^T   (tf32 warp-MMA)
    gemm_mma<<<gemm_big, 256, GEMM_MMA_SMEM>>>(S1, Wc, out, x, S1, BT, Dd, Dd);

    // ---- stage 2: gist rotation ----
    gist_cs_kernel<<<(Bb * DH + 255) / 256, 256>>>(gist_theta, gist_mag, gist_weights,
                                                   gist_strength, gc, gs);
    gist_fused_kernel<<<BT, 256>>>(out, ln_gist_w, ln_gist_b, gr_ln_w, gr_ln_b, gc, gs);

    // ---- stage 3: gist cross-attention ----
    pack_gist_in<<<(64 * KPAD + 255) / 256, 256>>>(gist_theta, gist_mag, packin);
    pad_W_kernel<<<(Dd * KPAD + 255) / 256, 256>>>(gist_up_W, Wpad);
    sgemm_nt<<<gemm_small, 256>>>(packin, Wpad, repr, nullptr, nullptr, gist_up_b,
                                  64, Dd, KPAD);
    sgemm_nt<<<gemm_small, 256>>>(repr, Wk, Khb, nullptr, nullptr, nullptr, 64, Dd, Dd);
    sgemm_nt<<<gemm_small, 256>>>(repr, Wv, Vb, nullptr, nullptr, nullptr, 64, Dd, Dd);
    ln_kernel<<<BT, 256>>>(out, S0, ln_gca_w, ln_gca_b, 1);
    // Q = ln @ Wq^T   (tf32 warp-MMA)
    gemm_mma<<<gemm_big, 256, GEMM_MMA_SMEM>>>(S0, Wq_r, S1, nullptr, nullptr, BT, Dd, Dd);
    attn_kernel<<<dim3(Tt / 8, Bb * NH), 256>>>(S1, Khb, Vb, S0);
    // out += ctx @ Wo^T   (tf32 warp-MMA)
    gemm_mma<<<gemm_big, 256, GEMM_MMA_SMEM>>>(S0, Wo_r, out, out, nullptr, BT, Dd, Dd);
}

// round 6
// speedup vs baseline: 5.0241x; 1.6946x over previous
#include <cuda_runtime.h>
#include <math.h>
#include <stdint.h>

// Problem constants
#define Bb 4
#define Tt 2048
#define Dd 2048
#define DH 1024
#define KK 16
#define NH 16
#define HD 128
#define BT (Bb*Tt)          // 8192 rows
#define KPAD 1088           // dh+1 padded so KPAD/8 splits are BK-multiples
#define NSPLIT 8

// ---------------- scratch (device globals; no allocation) ----------------
__device__ float g_S0[(size_t)BT * Dd];     // ln outputs / ctx
__device__ float g_S1[(size_t)BT * Dd];     // sheaf pre / Q
__device__ float g_Wr[3ull * Dd * Dd];      // tf32-rounded corr_W / Wq / Wo
__device__ float g_repr[64 * Dd];           // gist_repr
__device__ float g_Kh[64 * Dd];
__device__ float g_Vv[64 * Dd];
__device__ float g_packin[64 * KPAD];
__device__ float g_Wpad[Dd * KPAD];
__device__ float g_part[NSPLIT * 64 * Dd];  // split-K partials
__device__ float g_shc[4 * DH];
__device__ float g_shs[4 * DH];
__device__ float g_gc[Bb * DH];
__device__ float g_gs[Bb * DH];

// ---------------- helpers ----------------
__device__ __forceinline__ uint32_t smem_u32(const void* p) {
    uint32_t a;
    asm("{ .reg .u64 t; cvta.to.shared.u64 t, %1; cvt.u32.u64 %0, t; }" : "=r"(a) : "l"(p));
    return a;
}
__device__ __forceinline__ float rtf(float x) {   // round-to-nearest tf32
    uint32_t u;
    asm("cvt.rna.tf32.f32 %0, %1;" : "=r"(u) : "f"(x));
    return __uint_as_float(u);
}
__device__ __forceinline__ void cp16(uint32_t dst, const void* src) {
    asm volatile("cp.async.cg.shared.global [%0], [%1], 16;" :: "r"(dst), "l"(src));
}
__device__ __forceinline__ void ldsm_x4(uint32_t& r0, uint32_t& r1, uint32_t& r2, uint32_t& r3,
                                        uint32_t addr) {
    asm volatile("ldmatrix.sync.aligned.m8n8.x4.b16 {%0,%1,%2,%3}, [%4];"
                 : "=r"(r0), "=r"(r1), "=r"(r2), "=r"(r3) : "r"(addr));
}
__device__ __forceinline__ void mma_tf32_16n8k8(float& c0, float& c1, float& c2, float& c3,
                                                uint32_t a0, uint32_t a1, uint32_t a2, uint32_t a3,
                                                uint32_t b0, uint32_t b1) {
    asm volatile(
        "mma.sync.aligned.m16n8k8.row.col.f32.tf32.tf32.f32 "
        "{%0,%1,%2,%3}, {%4,%5,%6,%7}, {%8,%9}, {%0,%1,%2,%3};"
        : "+f"(c0), "+f"(c1), "+f"(c2), "+f"(c3)
        : "r"(a0), "r"(a1), "r"(a2), "r"(a3), "r"(b0), "r"(b1));
}

// ============== tf32 warp-MMA NT GEMM (ldmatrix + swizzle): C = A @ W^T (+add1)(+add2) ==============
// A: [M,K] row-major, W: [N,K] row-major, operands pre-rounded to tf32.
// M%128==0, N%128==0, K%32==0. 256 threads, 128x128 tile, K-chunk 32, 3-stage cp.async.
// Stage: As[128 rows][32 floats swizzled] (16KB) + Bs (16KB). Swizzle: 16B-chunk ^= (row&7).
#define KC 32
#define HALF_STAGE 16384
#define STAGE_BYTES 32768
#define NSTAGE 3
#define GEMM_MMA_SMEM (NSTAGE * STAGE_BYTES)   // 98304

__global__ void __launch_bounds__(256, 2) gemm_mma(const float* __restrict__ A,
                                                   const float* __restrict__ W,
                                                   float* __restrict__ C,
                                                   const float* __restrict__ add1,
                                                   const float* __restrict__ add2,
                                                   int M, int N, int K)
{
    extern __shared__ char dyn[];
    const int tid = threadIdx.x;
    const int bm = blockIdx.y * 128;
    const int bn = blockIdx.x * 128;
    const int nt = K >> 5;

    const int lane = tid & 31, wid = tid >> 5;
    const int wm = wid & 1, wn = wid >> 1;      // warp tile: 64 (m) x 32 (n)
    const int gid = lane >> 2, tig = lane & 3;
    const int am0 = wm * 64;
    const int bn0 = wn * 32;

    const uint32_t tile0 = smem_u32(dyn);
    const float* Abase = A + (size_t)bm * K;
    const float* Wbase = W + (size_t)bn * K;

    // ldmatrix per-thread address components
    const int lrow = lane & 7, lmat = lane >> 3;
    uint32_t aoff[4]; int arm[4];
#pragma unroll
    for (int mf = 0; mf < 4; mf++) {
        int r = am0 + mf * 16 + ((lmat & 1) << 3) + lrow;
        aoff[mf] = (uint32_t)(r * 128);
        arm[mf] = r & 7;
    }
    const int achunk_add = lmat >> 1;
    uint32_t boff[2]; int brm[2];
#pragma unroll
    for (int p = 0; p < 2; p++) {
        int r = bn0 + ((p * 2 + (lmat >> 1)) << 3) + lrow;
        boff[p] = (uint32_t)(r * 128);
        brm[p] = r & 7;
    }
    const int bchunk_add = lmat & 1;

    float acc[4][4][4];
#pragma unroll
    for (int i = 0; i < 4; i++)
#pragma unroll
        for (int j = 0; j < 4; j++)
#pragma unroll
            for (int r = 0; r < 4; r++) acc[i][j][r] = 0.f;

    auto load_stage = [&](int kt) {
        uint32_t base = tile0 + (kt % NSTAGE) * STAGE_BYTES;
#pragma unroll
        for (int i = 0; i < 4; i++) {
            int c = i * 256 + tid;               // 0..1023
            int row = c >> 3, ch = c & 7;
            uint32_t dof = (uint32_t)(row * 128 + ((ch ^ (row & 7)) << 4));
            cp16(base + dof,              Abase + (size_t)row * K + kt * KC + ch * 4);
            cp16(base + HALF_STAGE + dof, Wbase + (size_t)row * K + kt * KC + ch * 4);
        }
        asm volatile("cp.async.commit_group;" ::: "memory");
    };

    load_stage(0);
    if (nt > 1) load_stage(1);

    for (int kt = 0; kt < nt; kt++) {
        if (kt + 1 < nt) asm volatile("cp.async.wait_group 1;" ::: "memory");
        else             asm volatile("cp.async.wait_group 0;" ::: "memory");
        __syncthreads();
        if (kt + 2 < nt) load_stage(kt + 2);

        uint32_t As_u = tile0 + (kt % NSTAGE) * STAGE_BYTES;
        uint32_t Bs_u = As_u + HALF_STAGE;
#pragma unroll
        for (int ks = 0; ks < 4; ks++) {
            uint32_t a[4][4], b[4][2];
#pragma unroll
            for (int mf = 0; mf < 4; mf++) {
                uint32_t addr = As_u + aoff[mf] +
                                (uint32_t)(((2 * ks + achunk_add) ^ arm[mf]) << 4);
                ldsm_x4(a[mf][0], a[mf][1], a[mf][2], a[mf][3], addr);
            }
#pragma unroll
            for (int p = 0; p < 2; p++) {
                uint32_t addr = Bs_u + boff[p] +
                                (uint32_t)(((2 * ks + bchunk_add) ^ brm[p]) << 4);
                ldsm_x4(b[2 * p][0], b[2 * p][1], b[2 * p + 1][0], b[2 * p + 1][1], addr);
            }
#pragma unroll
            for (int mf = 0; mf < 4; mf++)
#pragma unroll
                for (int nf = 0; nf < 4; nf++)
                    mma_tf32_16n8k8(acc[mf][nf][0], acc[mf][nf][1],
                                    acc[mf][nf][2], acc[mf][nf][3],
                                    a[mf][0], a[mf][1], a[mf][2], a[mf][3],
                                    b[nf][0], b[nf][1]);
        }
    }

    // epilogue: float2 stores with fused residual adds
#pragma unroll
    for (int mf = 0; mf < 4; mf++) {
        int row0 = bm + am0 + mf * 16 + gid;
        size_t ro0 = (size_t)row0 * N;
        size_t ro1 = ro0 + (size_t)8 * N;
#pragma unroll
        for (int nf = 0; nf < 4; nf++) {
            int col = bn + bn0 + nf * 8 + tig * 2;
            float2 v0 = make_float2(acc[mf][nf][0], acc[mf][nf][1]);
            float2 v1 = make_float2(acc[mf][nf][2], acc[mf][nf][3]);
            if (add1) {
                float2 t0 = *(const float2*)(add1 + ro0 + col);
                float2 t1 = *(const float2*)(add1 + ro1 + col);
                v0.x += t0.x; v0.y += t0.y; v1.x += t1.x; v1.y += t1.y;
            }
            if (add2) {
                float2 t0 = *(const float2*)(add2 + ro0 + col);
                float2 t1 = *(const float2*)(add2 + ro1 + col);
                v0.x += t0.x; v0.y += t0.y; v1.x += t1.x; v1.y += t1.y;
            }
            *(float2*)(C + ro0 + col) = v0;
            *(float2*)(C + ro1 + col) = v1;
        }
    }
}

// ---------------- round a weight matrix to tf32 (rna) ----------------
__global__ void round_w(const float* __restrict__ in, float* __restrict__ out, int n4)
{
    int i = blockIdx.x * blockDim.x + threadIdx.x;
    if (i >= n4) return;
    float4 v = ((const float4*)in)[i];
    v.x = rtf(v.x); v.y = rtf(v.y); v.z = rtf(v.z); v.w = rtf(v.w);
    ((float4*)out)[i] = v;
}

// ---------------- block reduction (sum of two values) ----------------
__device__ __forceinline__ void block_reduce2(float& a, float& b, float* sh)
{
    __syncthreads();
#pragma unroll
    for (int o = 16; o > 0; o >>= 1) {
        a += __shfl_xor_sync(0xffffffffu, a, o);
        b += __shfl_xor_sync(0xffffffffu, b, o);
    }
    int warp = threadIdx.x >> 5, lane = threadIdx.x & 31;
    if (lane == 0) { sh[warp] = a; sh[8 + warp] = b; }
    __syncthreads();
    if (threadIdx.x < 32) {
        float aa = (lane < 8) ? sh[lane] : 0.f;
        float bb = (lane < 8) ? sh[8 + lane] : 0.f;
#pragma unroll
        for (int o = 4; o > 0; o >>= 1) {
            aa += __shfl_xor_sync(0xffffffffu, aa, o);
            bb += __shfl_xor_sync(0xffffffffu, bb, o);
        }
        if (lane == 0) { sh[16] = aa; sh[17] = bb; }
    }
    __syncthreads();
    a = sh[16]; b = sh[17];
}

// ---------------- LayerNorm (optionally tf32-round the store) ----------------
__global__ void __launch_bounds__(256) ln_kernel(const float* __restrict__ x,
                                                 float* __restrict__ y,
                                                 const float* __restrict__ w,
                                                 const float* __restrict__ b,
                                                 int round_out)
{
    __shared__ float sh[32];
    size_t row = blockIdx.x;
    const float* xr = x + row * Dd;
    float v[8]; float s = 0.f, s2 = 0.f;
#pragma unroll
    for (int i = 0; i < 8; i++) {
        v[i] = xr[threadIdx.x + (i << 8)];
        s += v[i]; s2 += v[i] * v[i];
    }
    block_reduce2(s, s2, sh);
    float mu = s * (1.f / Dd);
    float inv = rsqrtf(s2 * (1.f / Dd) - mu * mu + 1e-5f);
    float* yr = y + row * Dd;
#pragma unroll
    for (int i = 0; i < 8; i++) {
        int idx = threadIdx.x + (i << 8);
        float o = (v[i] - mu) * inv * w[idx] + b[idx];
        yr[idx] = round_out ? rtf(o) : o;
    }
}

// ---------------- cos/sin of sheaf thetas ----------------
__global__ void sheaf_cs_kernel(const float* __restrict__ th,
                                float* __restrict__ c, float* __restrict__ s)
{
    int i = blockIdx.x * blockDim.x + threadIdx.x;
    if (i < 4 * DH) { float t = th[i]; c[i] = cosf(t); s[i] = sinf(t); }
}

// ---------------- sheaf: pre = xln - |alpha| * lap (tf32-rounded) ----------------
__global__ void __launch_bounds__(256) sheaf_pre_kernel(const float* __restrict__ xln,
                                                        float* __restrict__ pre,
                                                        const float* __restrict__ cs,
                                                        const float* __restrict__ sn,
                                                        const float* __restrict__ alpha_p)
{
    int row = blockIdx.x;
    int b = row / Tt, t = row % Tt;
    float a = fabsf(alpha_p[0]);
    const float* xr = xln + (size_t)row * Dd;
    float* pr = pre + (size_t)row * Dd;
#pragma unroll
    for (int ii = 0; ii < 4; ii++) {
        int j = threadIdx.x + (ii << 8);
        float xre = xr[j], xim = xr[j + DH];
        float lr = 4.f * xre, li = 4.f * xim;
#pragma unroll
        for (int idx = 0; idx < 4; idx++) {
            int tn = t + (idx - 3);
            float yr = 0.f, yi = 0.f;
            if (tn >= 0) {
                const float* y = xln + ((size_t)b * Tt + tn) * Dd;
                yr = y[j]; yi = y[j + DH];
            }
            float c = cs[idx * DH + j], ss = sn[idx * DH + j];
            lr -= yr * c + yi * ss;
            li -= yi * c - yr * ss;
        }
        pr[j]      = rtf(xre - a * lr);
        pr[j + DH] = rtf(xim - a * li);
    }
}

// ---------------- gist angle cos/sin per (batch, dh) ----------------
__global__ void gist_cs_kernel(const float* __restrict__ gt,
                               const float* __restrict__ gm,
                               const float* __restrict__ gw,
                               const float* __restrict__ strength,
                               float* __restrict__ c, float* __restrict__ s)
{
    int i = blockIdx.x * blockDim.x + threadIdx.x;
    if (i >= Bb * DH) return;
    int b = i / DH, j = i % DH;
    float sig = 1.f / (1.f + expf(-strength[0]));
    float wsum = 0.f, th = 0.f;
#pragma unroll
    for (int k = 0; k < KK; k++) {
        float w = gw[b * KK + k] * gm[b * KK + k];
        wsum += w;
        th += w * gt[(size_t)(b * KK + k) * DH + j];
    }
    th = th / (wsum + 1e-8f) * sig;
    c[i] = cosf(th); s[i] = sinf(th);
}

// ---------------- fused: xn=LN(x); rot=rotate(xn); x += LN(rot) - xn ----------------
__global__ void __launch_bounds__(256) gist_fused_kernel(float* __restrict__ x,
    const float* __restrict__ lnw, const float* __restrict__ lnb,
    const float* __restrict__ grw, const float* __restrict__ grb,
    const float* __restrict__ gc, const float* __restrict__ gs)
{
    __shared__ float sh[32];
    size_t row = blockIdx.x;
    int b = blockIdx.x / Tt;
    float* xr = x + row * Dd;
    float v[8]; float s = 0.f, s2 = 0.f;
#pragma unroll
    for (int i = 0; i < 8; i++) {
        v[i] = xr[threadIdx.x + (i << 8)];
        s += v[i]; s2 += v[i] * v[i];
    }
    block_reduce2(s, s2, sh);
    float mu = s * (1.f / Dd);
    float inv = rsqrtf(s2 * (1.f / Dd) - mu * mu + 1e-5f);
    float xn[8];
#pragma unroll
    for (int i = 0; i < 8; i++) {
        int idx = threadIdx.x + (i << 8);
        xn[i] = (v[i] - mu) * inv * lnw[idx] + lnb[idx];
    }
    float rot[8]; float rs = 0.f, rs2 = 0.f;
#pragma unroll
    for (int i = 0; i < 4; i++) {
        int j = threadIdx.x + (i << 8);
        float c = gc[b * DH + j], sn = gs[b * DH + j];
        float r = xn[i], im = xn[i + 4];
        rot[i]     = r * c - im * sn;
        rot[i + 4] = r * sn + im * c;
    }
#pragma unroll
    for (int i = 0; i < 8; i++) { rs += rot[i]; rs2 += rot[i] * rot[i]; }
    block_reduce2(rs, rs2, sh);
    float mu2 = rs * (1.f / Dd);
    float inv2 = rsqrtf(rs2 * (1.f / Dd) - mu2 * mu2 + 1e-5f);
#pragma unroll
    for (int i = 0; i < 8; i++) {
        int idx = threadIdx.x + (i << 8);
        xr[idx] = v[i] + ((rot[i] - mu2) * inv2 * grw[idx] + grb[idx]) - xn[i];
    }
}

// ---------------- pack concat([gist_theta, gist_mag]) into [64, KPAD] ----------------
__global__ void pack_gist_in(const float* __restrict__ gt, const float* __restrict__ gm,
                             float* __restrict__ out)
{
    int i = blockIdx.x * blockDim.x + threadIdx.x;
    if (i >= 64 * KPAD) return;
    int r = i / KPAD, f = i % KPAD;
    float v = 0.f;
    if (f < DH) v = gt[(size_t)r * DH + f];
    else if (f == DH) v = gm[r];
    out[i] = v;
}

__global__ void pad_W_kernel(const float* __restrict__ W, float* __restrict__ out)
{
    int i = blockIdx.x * blockDim.x + threadIdx.x;
    if (i >= Dd * KPAD) return;
    int o = i / KPAD, f = i % KPAD;
    out[i] = (f < DH + 1) ? W[(size_t)o * (DH + 1) + f] : 0.f;
}

// ---------------- split-K SIMT GEMM for M=64: part[s] = A @ W^T (K-slice s) ----------------
__global__ void __launch_bounds__(256) splitk_nt(const float* __restrict__ A,
                                                 const float* __restrict__ W,
                                                 float* __restrict__ part,
                                                 int M, int N, int Ktot, int Kchunk)
{
    __shared__ float As[2][8][128];
    __shared__ float Bs[2][8][128];
    const int tid = threadIdx.x;
    const int bn = blockIdx.x * 128;
    const int kofs = blockIdx.y * Kchunk;
    const int lrow = tid >> 1;
    const int lcol = (tid & 1) << 2;
    const int tx = tid & 15;
    const int ty = tid >> 4;
    const int tm0 = ty * 8, tn0 = tx * 8;

    const float* Aptr = A + (size_t)lrow * Ktot + kofs + lcol;
    const float* Wptr = W + (size_t)(bn + lrow) * Ktot + kofs + lcol;
    const bool a_ok = lrow < M;

    float acc[8][8];
#pragma unroll
    for (int i = 0; i < 8; i++)
#pragma unroll
        for (int j = 0; j < 8; j++) acc[i][j] = 0.f;

    float4 pa = a_ok ? *(const float4*)Aptr : make_float4(0.f, 0.f, 0.f, 0.f);
    float4 pb = *(const float4*)Wptr;
    As[0][lcol + 0][lrow] = pa.x; As[0][lcol + 1][lrow] = pa.y;
    As[0][lcol + 2][lrow] = pa.z; As[0][lcol + 3][lrow] = pa.w;
    Bs[0][lcol + 0][lrow] = pb.x; Bs[0][lcol + 1][lrow] = pb.y;
    Bs[0][lcol + 2][lrow] = pb.z; Bs[0][lcol + 3][lrow] = pb.w;
    __syncthreads();

    const int ntiles = Kchunk >> 3;
    for (int kt = 0; kt < ntiles; kt++) {
        int buf = kt & 1;
        if (kt + 1 < ntiles) {
            pa = a_ok ? *(const float4*)(Aptr + (size_t)(kt + 1) * 8)
                      : make_float4(0.f, 0.f, 0.f, 0.f);
            pb = *(const float4*)(Wptr + (size_t)(kt + 1) * 8);
        }
#pragma unroll
        for (int k = 0; k < 8; k++) {
            float4 a0 = *(const float4*)&As[buf][k][tm0];
            float4 a1 = *(const float4*)&As[buf][k][tm0 + 4];
            float4 b0 = *(const float4*)&Bs[buf][k][tn0];
            float4 b1 = *(const float4*)&Bs[buf][k][tn0 + 4];
            float af[8] = {a0.x, a0.y, a0.z, a0.w, a1.x, a1.y, a1.z, a1.w};
            float bf[8] = {b0.x, b0.y, b0.z, b0.w, b1.x, b1.y, b1.z, b1.w};
#pragma unroll
            for (int i = 0; i < 8; i++)
#pragma unroll
                for (int j = 0; j < 8; j++)
                    acc[i][j] += af[i] * bf[j];
        }
        if (kt + 1 < ntiles) {
            int nb = buf ^ 1;
            As[nb][lcol + 0][lrow] = pa.x; As[nb][lcol + 1][lrow] = pa.y;
            As[nb][lcol + 2][lrow] = pa.z; As[nb][lcol + 3][lrow] = pa.w;
            Bs[nb][lcol + 0][lrow] = pb.x; Bs[nb][lcol + 1][lrow] = pb.y;
            Bs[nb][lcol + 2][lrow] = pb.z; Bs[nb][lcol + 3][lrow] = pb.w;
            __syncthreads();
        }
    }

    float* po = part + (size_t)blockIdx.y * M * N;
#pragma unroll
    for (int i = 0; i < 8; i++) {
        int gm = tm0 + i;
        if (gm < M) {
#pragma unroll
            for (int j = 0; j < 8; j += 4) {
                int gn = bn + tn0 + j;
                float4 v = make_float4(acc[i][j], acc[i][j + 1], acc[i][j + 2], acc[i][j + 3]);
                *(float4*)(po + (size_t)gm * N + gn) = v;
            }
        }
    }
}

// ---------------- reduce split-K partials (+optional bias) ----------------
__global__ void reduce_part(const float* __restrict__ part, float* __restrict__ C,
                            const float* __restrict__ bias, int MN, int N)
{
    int i = blockIdx.x * blockDim.x + threadIdx.x;
    if (i >= MN) return;
    float s = bias ? bias[i % N] : 0.f;
#pragma unroll
    for (int sp = 0; sp < NSPLIT; sp++) s += part[(size_t)sp * MN + i];
    C[i] = s;
}

// ---------------- tiny cross-attention (ctx tf32-rounded for Wo GEMM) ----------------
__global__ void __launch_bounds__(256) attn_kernel(const float* __restrict__ Q,
                                                   const float* __restrict__ Kh,
                                                   const float* __restrict__ Vv,
                                                   float* __restrict__ ctx)
{
    __shared__ float ks[KK][HD];
    __shared__ float vs[KK][HD];
    int bh = blockIdx.y;
    int b = bh >> 4, h = bh & 15;
    for (int i = threadIdx.x; i < KK * HD; i += 256) {
        int k = i >> 7, dd = i & 127;
        size_t off = ((size_t)(b * KK + k)) * Dd + h * HD + dd;
        ks[k][dd] = Kh[off];
        vs[k][dd] = Vv[off];
    }
    __syncthreads();
    int warp = threadIdx.x >> 5, lane = threadIdx.x & 31;
    int t = blockIdx.x * 8 + warp;
    size_t qoff = ((size_t)(b * Tt + t)) * Dd + h * HD + lane * 4;
    float4 q = *(const float4*)(Q + qoff);
    float sc[KK];
#pragma unroll
    for (int k = 0; k < KK; k++) {
        float4 kv = *(const float4*)&ks[k][lane * 4];
        float d = q.x * kv.x + q.y * kv.y + q.z * kv.z + q.w * kv.w;
#pragma unroll
        for (int o = 16; o > 0; o >>= 1) d += __shfl_xor_sync(0xffffffffu, d, o);
        sc[k] = d * 0.088388347648318447f;
    }
    float m = sc[0];
#pragma unroll
    for (int k = 1; k < KK; k++) m = fmaxf(m, sc[k]);
    float ssum = 0.f;
#pragma unroll
    for (int k = 0; k < KK; k++) { sc[k] = expf(sc[k] - m); ssum += sc[k]; }
    float rinv = 1.f / ssum;
    float4 o = make_float4(0.f, 0.f, 0.f, 0.f);
#pragma unroll
    for (int k = 0; k < KK; k++) {
        float p = sc[k] * rinv;
        float4 vv = *(const float4*)&vs[k][lane * 4];
        o.x += p * vv.x; o.y += p * vv.y; o.z += p * vv.z; o.w += p * vv.w;
    }
    o.x = rtf(o.x); o.y = rtf(o.y); o.z = rtf(o.z); o.w = rtf(o.w);
    *(float4*)(ctx + qoff) = o;
}

// ---------------- orchestration ----------------
extern "C" void kernel_launch(void* const* d_in, const int* in_sizes, int n_in,
                              void* d_out, int out_size)
{
    const float* x            = (const float*)d_in[0];
    const float* gist_theta   = (const float*)d_in[1];
    const float* gist_mag     = (const float*)d_in[2];
    const float* gist_weights = (const float*)d_in[3];
    const float* ln_sheaf_w   = (const float*)d_in[4];
    const float* ln_sheaf_b   = (const float*)d_in[5];
    const float* sheaf_thetas = (const float*)d_in[6];
    const float* alpha        = (const float*)d_in[7];
    const float* corr_W       = (const float*)d_in[8];
    const float* ln_gist_w    = (const float*)d_in[9];
    const float* ln_gist_b    = (const float*)d_in[10];
    const float* gist_strength= (const float*)d_in[11];
    const float* gr_ln_w      = (const float*)d_in[12];
    const float* gr_ln_b      = (const float*)d_in[13];
    const float* ln_gca_w     = (const float*)d_in[14];
    const float* ln_gca_b     = (const float*)d_in[15];
    const float* Wq           = (const float*)d_in[16];
    const float* Wk           = (const float*)d_in[17];
    const float* Wv           = (const float*)d_in[18];
    const float* Wo           = (const float*)d_in[19];
    const float* gist_up_W    = (const float*)d_in[20];
    const float* gist_up_b    = (const float*)d_in[21];
    float* out = (float*)d_out;

    float *S0, *S1, *Wr, *repr, *Khb, *Vb, *packin, *Wpad, *part, *shc, *shs, *gc, *gs;
    cudaGetSymbolAddress((void**)&S0, g_S0);
    cudaGetSymbolAddress((void**)&S1, g_S1);
    cudaGetSymbolAddress((void**)&Wr, g_Wr);
    cudaGetSymbolAddress((void**)&repr, g_repr);
    cudaGetSymbolAddress((void**)&Khb, g_Kh);
    cudaGetSymbolAddress((void**)&Vb, g_Vv);
    cudaGetSymbolAddress((void**)&packin, g_packin);
    cudaGetSymbolAddress((void**)&Wpad, g_Wpad);
    cudaGetSymbolAddress((void**)&part, g_part);
    cudaGetSymbolAddress((void**)&shc, g_shc);
    cudaGetSymbolAddress((void**)&shs, g_shs);
    cudaGetSymbolAddress((void**)&gc, g_gc);
    cudaGetSymbolAddress((void**)&gs, g_gs);

    float* Wc = Wr;                        // rounded corr_W
    float* Wq_r = Wr + (size_t)Dd * Dd;    // rounded Wq
    float* Wo_r = Wr + 2ull * Dd * Dd;     // rounded Wo

    cudaFuncSetAttribute(gemm_mma, cudaFuncAttributeMaxDynamicSharedMemorySize,
                         GEMM_MMA_SMEM);

    dim3 gemm_big(Dd / 128, BT / 128);   // (16, 64)
    dim3 sk_grid(Dd / 128, NSPLIT);      // (16, 8)
    const int WN4 = Dd * Dd / 4;
    const int MN64 = 64 * Dd;

    // ---- round GEMM weights to tf32 (upfront, independent) ----
    round_w<<<(WN4 + 255) / 256, 256>>>(corr_W, Wc, WN4);
    round_w<<<(WN4 + 255) / 256, 256>>>(Wq, Wq_r, WN4);
    round_w<<<(WN4 + 255) / 256, 256>>>(Wo, Wo_r, WN4);

    // ---- stage 1: sheaf ----
    ln_kernel<<<BT, 256>>>(x, S0, ln_sheaf_w, ln_sheaf_b, 0);
    sheaf_cs_kernel<<<(4 * DH + 255) / 256, 256>>>(sheaf_thetas, shc, shs);
    sheaf_pre_kernel<<<BT, 256>>>(S0, S1, shc, shs, alpha);
    // out = x + pre + pre @ corr_W^T   (tf32 warp-MMA + ldmatrix)
    gemm_mma<<<gemm_big, 256, GEMM_MMA_SMEM>>>(S1, Wc, out, x, S1, BT, Dd, Dd);

    // ---- stage 2: gist rotation ----
    gist_cs_kernel<<<(Bb * DH + 255) / 256, 256>>>(gist_theta, gist_mag, gist_weights,
                                                   gist_strength, gc, gs);
    gist_fused_kernel<<<BT, 256>>>(out, ln_gist_w, ln_gist_b, gr_ln_w, gr_ln_b, gc, gs);

    // ---- stage 3: gist cross-attention ----
    pack_gist_in<<<(64 * KPAD + 255) / 256, 256>>>(gist_theta, gist_mag, packin);
    pad_W_kernel<<<(Dd * KPAD + 255) / 256, 256>>>(gist_up_W, Wpad);
    // gist_repr = packin @ Wpad^T + bias   (split-K)
    splitk_nt<<<sk_grid, 256>>>(packin, Wpad, part, 64, Dd, KPAD, KPAD / NSPLIT);
    reduce_part<<<(MN64 + 255) / 256, 256>>>(part, repr, gist_up_b, MN64, Dd);
    // Kh = repr @ Wk^T, V = repr @ Wv^T   (split-K)
    splitk_nt<<<sk_grid, 256>>>(repr, Wk, part, 64, Dd, Dd, Dd / NSPLIT);
    reduce_part<<<(MN64 + 255) / 256, 256>>>(part, Khb, nullptr, MN64, Dd);
    splitk_nt<<<sk_grid, 256>>>(repr, Wv, part, 64, Dd, Dd, Dd / NSPLIT);
    reduce_part<<<(MN64 + 255) / 256, 256>>>(part, Vb, nullptr, MN64, Dd);

    ln_kernel<<<BT, 256>>>(out, S0, ln_gca_w, ln_gca_b, 1);
    // Q = ln @ Wq^T   (tf32 warp-MMA + ldmatrix)
    gemm_mma<<<gemm_big, 256, GEMM_MMA_SMEM>>>(S0, Wq_r, S1, nullptr, nullptr, BT, Dd, Dd);
    attn_kernel<<<dim3(Tt / 8, Bb * NH), 256>>>(S1, Khb, Vb, S0);
    // out += ctx @ Wo^T   (tf32 warp-MMA + ldmatrix)
    gemm_mma<<<gemm_big, 256, GEMM_MMA_SMEM>>>(S0, Wo_r, out, out, nullptr, BT, Dd, Dd);
}